// round 3
// baseline (speedup 1.0000x reference)
#include <cuda_runtime.h>

// Problem dims (fixed by setup_inputs)
#define DD 2048      // D
#define OO 8192      // O
#define TT 4096      // T

#define WR_PARTS 32  // word-dim split for stage 1
#define V_PARTS  8   // d-dim split for stage 2

// Scratch (allocation-free rule: __device__ globals)
__device__ float g_part_wr[WR_PARTS * DD];
__device__ float g_wr[DD];
__device__ float g_part_v[V_PARTS * OO];
__device__ float g_v[OO];

// ---------------------------------------------------------------------------
// K1: partial weighted row-sums of x.
// grid = (DD/256 = 8 col-tiles, WR_PARTS = 32 word-tiles), block = 256.
// Each word-tile covers 64 words. wr[d] = sum_{word>=1} hrf[DD-word]*x[word,d]
// ---------------------------------------------------------------------------
__global__ __launch_bounds__(256)
void k1_partial_wr(const float* __restrict__ x, const float* __restrict__ hrf) {
    __shared__ float s_c[64];
    const int col = blockIdx.x * 256 + threadIdx.x;
    const int w0  = blockIdx.y * 64;

    // Stage the 64 coefficients for this word-tile (word 0 contributes 0).
    if (threadIdx.x < 64) {
        int word = w0 + threadIdx.x;
        s_c[threadIdx.x] = (word >= 1) ? hrf[DD - word] : 0.0f;
    }
    __syncthreads();

    float acc = 0.0f;
    #pragma unroll 8
    for (int i = 0; i < 64; ++i) {
        acc = fmaf(s_c[i], x[(size_t)(w0 + i) * DD + col], acc);
    }
    g_part_wr[blockIdx.y * DD + col] = acc;
}

// K1r: reduce 32 partials -> g_wr. grid = 8, block = 256.
__global__ __launch_bounds__(256)
void k1_reduce_wr() {
    const int col = blockIdx.x * 256 + threadIdx.x;
    float acc = 0.0f;
    #pragma unroll
    for (int p = 0; p < WR_PARTS; ++p) acc += g_part_wr[p * DD + col];
    g_wr[col] = acc;
}

// ---------------------------------------------------------------------------
// K2: partial GEMV v = wr @ weights.  weights is [DD, OO] row-major.
// grid = (OO/256 = 32 o-tiles, V_PARTS = 8 d-tiles of 256), block = 256.
// ---------------------------------------------------------------------------
__global__ __launch_bounds__(256)
void k2_partial_v(const float* __restrict__ weights) {
    __shared__ float s_wr[256];
    const int o  = blockIdx.x * 256 + threadIdx.x;
    const int d0 = blockIdx.y * 256;

    s_wr[threadIdx.x] = g_wr[d0 + threadIdx.x];
    __syncthreads();

    float acc = 0.0f;
    const float* __restrict__ wp = weights + (size_t)d0 * OO + o;
    #pragma unroll 8
    for (int i = 0; i < 256; ++i) {
        acc = fmaf(s_wr[i], wp[(size_t)i * OO], acc);
    }
    g_part_v[blockIdx.y * OO + o] = acc;
}

// K2r: reduce 8 partials -> g_v. grid = 32, block = 256.
__global__ __launch_bounds__(256)
void k2_reduce_v() {
    const int o = blockIdx.x * 256 + threadIdx.x;
    float acc = 0.0f;
    #pragma unroll
    for (int p = 0; p < V_PARTS; ++p) acc += g_part_v[p * OO + o];
    g_v[o] = acc;
}

// ---------------------------------------------------------------------------
// K3: out[t,o] = w_times_init[t,o] + v[o] + bias[t], float4-vectorized.
// One float4 per thread. TT*OO/4 = 8388608 threads -> 32768 blocks of 256.
// OO/4 = 2048 float4 per row -> row index via shift.
// ---------------------------------------------------------------------------
__global__ __launch_bounds__(256)
void k3_broadcast_add(const float4* __restrict__ w_init,
                      const float* __restrict__ bias,
                      float4* __restrict__ out) {
    const int idx = blockIdx.x * 256 + threadIdx.x;   // 0 .. 8388607
    const int t   = idx >> 11;                        // / (OO/4)
    const int o4  = idx & 2047;                       // % (OO/4)

    const float4 w = w_init[idx];
    const float4 v = reinterpret_cast<const float4*>(g_v)[o4];
    const float  b = __ldg(&bias[t]);

    float4 r;
    r.x = w.x + v.x + b;
    r.y = w.y + v.y + b;
    r.z = w.z + v.z + b;
    r.w = w.w + v.w + b;
    out[idx] = r;
}

// ---------------------------------------------------------------------------
// Input order (metadata): x[D*D], hrf_weight[D], weights[D*O], bias[T],
//                         w_times_init[T*O].  Output: float32 [T*O].
// ---------------------------------------------------------------------------
extern "C" void kernel_launch(void* const* d_in, const int* in_sizes, int n_in,
                              void* d_out, int out_size) {
    const float* x      = (const float*)d_in[0];
    const float* hrf    = (const float*)d_in[1];
    const float* wts    = (const float*)d_in[2];
    const float* bias   = (const float*)d_in[3];
    const float* w_init = (const float*)d_in[4];
    float* out = (float*)d_out;

    k1_partial_wr<<<dim3(DD / 256, WR_PARTS), 256>>>(x, hrf);
    k1_reduce_wr<<<DD / 256, 256>>>();
    k2_partial_v<<<dim3(OO / 256, V_PARTS), 256>>>(wts);
    k2_reduce_v<<<OO / 256, 256>>>();
    k3_broadcast_add<<<(TT * OO / 4) / 256, 256>>>(
        (const float4*)w_init, bias, (float4*)out);
}

// round 4
// speedup vs baseline: 1.2239x; 1.2239x over previous
#include <cuda_runtime.h>

// Problem dims (fixed by setup_inputs)
#define DD 2048      // D
#define OO 8192      // O
#define TT 4096      // T

#define WR_PARTS 64  // word-dim split for stage 1 (32 words per tile)
#define V_PARTS  16  // d-dim split for stage 2 (128 d per tile)

// Scratch (allocation-free rule: __device__ globals)
__device__ float g_part_wr[WR_PARTS * DD];   // 512 KB
__device__ float g_part_v[V_PARTS * OO];     // 512 KB
__device__ float g_v[OO];                    // 32 KB

// ---------------------------------------------------------------------------
// K1: partial weighted row-sums of x.
// grid = (DD/256 = 8 col-tiles, WR_PARTS = 64 word-tiles), block = 256.
// Each word-tile covers 32 words, fully unrolled -> high MLP.
// wr[d] = sum_{word>=1} hrf[DD-word] * x[word,d]
// ---------------------------------------------------------------------------
__global__ __launch_bounds__(256)
void k1_partial_wr(const float* __restrict__ x, const float* __restrict__ hrf) {
    __shared__ float s_c[32];
    const int col = blockIdx.x * 256 + threadIdx.x;
    const int w0  = blockIdx.y * 32;

    if (threadIdx.x < 32) {
        int word = w0 + threadIdx.x;
        s_c[threadIdx.x] = (word >= 1) ? hrf[DD - word] : 0.0f;  // word 0 contributes 0
    }
    __syncthreads();

    float acc = 0.0f;
    #pragma unroll
    for (int i = 0; i < 32; ++i) {
        acc = fmaf(s_c[i], x[(size_t)(w0 + i) * DD + col], acc);
    }
    g_part_wr[blockIdx.y * DD + col] = acc;
}

// ---------------------------------------------------------------------------
// K2: partial GEMV v = wr @ weights, with the wr-reduction FUSED as a
// prologue (reads the 64 partials from L2; buffer is reused by all o-tiles).
// grid = (OO/256 = 32 o-tiles, V_PARTS = 16 d-tiles of 128), block = 256.
// ---------------------------------------------------------------------------
__global__ __launch_bounds__(256)
void k2_partial_v(const float* __restrict__ weights) {
    __shared__ float s_wr[128];
    const int o  = blockIdx.x * 256 + threadIdx.x;
    const int d0 = blockIdx.y * 128;

    // Fused wr-reduce: threads 0..127 each finalize one wr element.
    if (threadIdx.x < 128) {
        float w = 0.0f;
        #pragma unroll
        for (int p = 0; p < WR_PARTS; ++p)
            w += g_part_wr[p * DD + d0 + threadIdx.x];
        s_wr[threadIdx.x] = w;
    }
    __syncthreads();

    float acc = 0.0f;
    const float* __restrict__ wp = weights + (size_t)d0 * OO + o;
    #pragma unroll 16
    for (int i = 0; i < 128; ++i) {
        acc = fmaf(s_wr[i], wp[(size_t)i * OO], acc);
    }
    g_part_v[blockIdx.y * OO + o] = acc;
}

// K2r: reduce 16 partials -> g_v. grid = 32, block = 256. (tiny, L2-resident)
__global__ __launch_bounds__(256)
void k2_reduce_v() {
    const int o = blockIdx.x * 256 + threadIdx.x;
    float acc = 0.0f;
    #pragma unroll
    for (int p = 0; p < V_PARTS; ++p) acc += g_part_v[p * OO + o];
    g_v[o] = acc;
}

// ---------------------------------------------------------------------------
// K3: out[t,o] = w_times_init[t,o] + v[o] + bias[t], float4-vectorized.
// Streaming hints on the 256 MiB w_init/out traffic (zero reuse) keep the
// hot g_v (32 KB) + bias (16 KB) lines resident.
// ---------------------------------------------------------------------------
__global__ __launch_bounds__(256)
void k3_broadcast_add(const float4* __restrict__ w_init,
                      const float* __restrict__ bias,
                      float4* __restrict__ out) {
    const int idx = blockIdx.x * 256 + threadIdx.x;   // 0 .. 8388607
    const int t   = idx >> 11;                        // / (OO/4)
    const int o4  = idx & 2047;                       // % (OO/4)

    const float4 w = __ldcs(&w_init[idx]);            // evict-first
    const float4 v = reinterpret_cast<const float4*>(g_v)[o4];
    const float  b = __ldg(&bias[t]);

    float4 r;
    r.x = w.x + v.x + b;
    r.y = w.y + v.y + b;
    r.z = w.z + v.z + b;
    r.w = w.w + v.w + b;
    __stcs(&out[idx], r);                             // streaming store
}

// ---------------------------------------------------------------------------
// Input order (metadata): x[D*D], hrf_weight[D], weights[D*O], bias[T],
//                         w_times_init[T*O].  Output: float32 [T*O].
// ---------------------------------------------------------------------------
extern "C" void kernel_launch(void* const* d_in, const int* in_sizes, int n_in,
                              void* d_out, int out_size) {
    const float* x      = (const float*)d_in[0];
    const float* hrf    = (const float*)d_in[1];
    const float* wts    = (const float*)d_in[2];
    const float* bias   = (const float*)d_in[3];
    const float* w_init = (const float*)d_in[4];
    float* out = (float*)d_out;

    k1_partial_wr<<<dim3(DD / 256, WR_PARTS), 256>>>(x, hrf);
    k2_partial_v<<<dim3(OO / 256, V_PARTS), 256>>>(wts);
    k2_reduce_v<<<OO / 256, 256>>>();
    k3_broadcast_add<<<(TT * OO / 4) / 256, 256>>>(
        (const float4*)w_init, bias, (float4*)out);
}

// round 5
// speedup vs baseline: 1.2756x; 1.0423x over previous
#include <cuda_runtime.h>

// Problem dims (fixed by setup_inputs)
#define DD 2048      // D
#define OO 8192      // O
#define TT 4096      // T

#define WR_PARTS 64  // word-dim split for stage 1 (32 words per tile)
#define V_PARTS  16  // d-dim split for stage 2 (128 d per tile)

// Scratch (allocation-free rule: __device__ globals)
__device__ float g_part_wr[WR_PARTS * DD];   // 512 KB
__device__ float g_part_v[V_PARTS * OO];     // 512 KB
__device__ float g_v[OO];                    // 32 KB

// ---------------------------------------------------------------------------
// K1: partial weighted row-sums of x.
// grid = (8 col-tiles, 64 word-tiles), block = 256. 32 words/tile, full unroll.
// wr[d] = sum_{word>=1} hrf[DD-word] * x[word,d]
// ---------------------------------------------------------------------------
__global__ __launch_bounds__(256)
void k1_partial_wr(const float* __restrict__ x, const float* __restrict__ hrf) {
    __shared__ float s_c[32];
    const int col = blockIdx.x * 256 + threadIdx.x;
    const int w0  = blockIdx.y * 32;

    if (threadIdx.x < 32) {
        int word = w0 + threadIdx.x;
        s_c[threadIdx.x] = (word >= 1) ? hrf[DD - word] : 0.0f;  // word 0 contributes 0
    }
    __syncthreads();

    float acc = 0.0f;
    #pragma unroll
    for (int i = 0; i < 32; ++i) {
        acc = fmaf(s_c[i], x[(size_t)(w0 + i) * DD + col], acc);
    }
    g_part_wr[blockIdx.y * DD + col] = acc;
}

// ---------------------------------------------------------------------------
// K2: partial GEMV v = wr @ weights, wr-reduction fused as prologue
// (64 partials are L2-resident, reused by all 32 o-tiles).
// grid = (32 o-tiles, 16 d-tiles of 128), block = 256.
// ---------------------------------------------------------------------------
__global__ __launch_bounds__(256)
void k2_partial_v(const float* __restrict__ weights) {
    __shared__ float s_wr[128];
    const int o  = blockIdx.x * 256 + threadIdx.x;
    const int d0 = blockIdx.y * 128;

    if (threadIdx.x < 128) {
        float w = 0.0f;
        #pragma unroll
        for (int p = 0; p < WR_PARTS; ++p)
            w += g_part_wr[p * DD + d0 + threadIdx.x];
        s_wr[threadIdx.x] = w;
    }
    __syncthreads();

    float acc = 0.0f;
    const float* __restrict__ wp = weights + (size_t)d0 * OO + o;
    #pragma unroll 16
    for (int i = 0; i < 128; ++i) {
        acc = fmaf(s_wr[i], wp[(size_t)i * OO], acc);
    }
    g_part_v[blockIdx.y * OO + o] = acc;
}

// K2r: reduce 16 partials -> g_v. grid = 32, block = 256. (tiny, L2-resident)
__global__ __launch_bounds__(256)
void k2_reduce_v() {
    const int o = blockIdx.x * 256 + threadIdx.x;
    float acc = 0.0f;
    #pragma unroll
    for (int p = 0; p < V_PARTS; ++p) acc += g_part_v[p * OO + o];
    g_v[o] = acc;
}

// ---------------------------------------------------------------------------
// K3: out[t,o] = w_times_init[t,o] + v[o] + bias[t].
// One block = one half-row (1024 consecutive float4s of one t):
//   - t constant per block -> single bias load, broadcast
//   - v segment identical for all blocks with same half -> L1/L2 hot
//   - each thread front-batches 4 strided float4 loads (MLP=4), then 4
//     streaming stores. Grid = TT*2 = 8192 blocks, block = 256.
// ---------------------------------------------------------------------------
__global__ __launch_bounds__(256)
void k3_broadcast_add(const float4* __restrict__ w_init,
                      const float* __restrict__ bias,
                      float4* __restrict__ out) {
    const int t    = blockIdx.x >> 1;
    const int half = blockIdx.x & 1;
    const size_t base = (size_t)blockIdx.x * 1024 + threadIdx.x;

    const float b = __ldg(&bias[t]);

    // Front-batched streaming loads of w_init (4 lines in flight per thread)
    const float4 w0 = __ldcs(&w_init[base]);
    const float4 w1 = __ldcs(&w_init[base + 256]);
    const float4 w2 = __ldcs(&w_init[base + 512]);
    const float4 w3 = __ldcs(&w_init[base + 768]);

    const float4* __restrict__ vp =
        reinterpret_cast<const float4*>(g_v) + half * 1024 + threadIdx.x;
    const float4 v0 = __ldg(&vp[0]);
    const float4 v1 = __ldg(&vp[256]);
    const float4 v2 = __ldg(&vp[512]);
    const float4 v3 = __ldg(&vp[768]);

    float4 r0, r1, r2, r3;
    r0.x = w0.x + v0.x + b; r0.y = w0.y + v0.y + b;
    r0.z = w0.z + v0.z + b; r0.w = w0.w + v0.w + b;
    r1.x = w1.x + v1.x + b; r1.y = w1.y + v1.y + b;
    r1.z = w1.z + v1.z + b; r1.w = w1.w + v1.w + b;
    r2.x = w2.x + v2.x + b; r2.y = w2.y + v2.y + b;
    r2.z = w2.z + v2.z + b; r2.w = w2.w + v2.w + b;
    r3.x = w3.x + v3.x + b; r3.y = w3.y + v3.y + b;
    r3.z = w3.z + v3.z + b; r3.w = w3.w + v3.w + b;

    __stcs(&out[base],       r0);
    __stcs(&out[base + 256], r1);
    __stcs(&out[base + 512], r2);
    __stcs(&out[base + 768], r3);
}

// ---------------------------------------------------------------------------
// Input order (metadata): x[D*D], hrf_weight[D], weights[D*O], bias[T],
//                         w_times_init[T*O].  Output: float32 [T*O].
// ---------------------------------------------------------------------------
extern "C" void kernel_launch(void* const* d_in, const int* in_sizes, int n_in,
                              void* d_out, int out_size) {
    const float* x      = (const float*)d_in[0];
    const float* hrf    = (const float*)d_in[1];
    const float* wts    = (const float*)d_in[2];
    const float* bias   = (const float*)d_in[3];
    const float* w_init = (const float*)d_in[4];
    float* out = (float*)d_out;

    k1_partial_wr<<<dim3(DD / 256, WR_PARTS), 256>>>(x, hrf);
    k2_partial_v<<<dim3(OO / 256, V_PARTS), 256>>>(wts);
    k2_reduce_v<<<OO / 256, 256>>>();
    k3_broadcast_add<<<TT * 2, 256>>>((const float4*)w_init, bias, (float4*)out);
}